// round 1
// baseline (speedup 1.0000x reference)
#include <cuda_runtime.h>
#include <math.h>

// Problem constants (fixed shapes per reference)
#define BB 131072
#define DD 64
#define KK 1024
#define DECAYF 0.99f
#define OMDF 0.01f
#define EPSV 1e-5f

// ---------------- scratch (static __device__: no allocation allowed) ----------------
__device__ float g_zn[(size_t)BB * DD];      // normalized z rows        (33.5 MB)
__device__ float g_znorm[BB];                // max(||z||, eps) per row
__device__ float g_enT[DD * KK];             // normalized embedding, TRANSPOSED [d][k]
__device__ float g_counts[KK];               // segment counts (float)
__device__ float g_dw[KK * DD];              // segment sums of z_n
__device__ float g_embed_unit[KK * DD];      // updated normalized codebook
__device__ int   g_codes[BB];                // argmax codes

// ---------------- helpers ----------------
__device__ __forceinline__ float warpsum(float v) {
#pragma unroll
    for (int o = 16; o; o >>= 1) v += __shfl_xor_sync(0xffffffffu, v, o);
    return v;
}

// ---------------- kernel 1: normalize z rows (warp per row) ----------------
__global__ void k_norm_z(const float* __restrict__ ze) {
    int w = (blockIdx.x * blockDim.x + threadIdx.x) >> 5;
    int lane = threadIdx.x & 31;
    if (w >= BB) return;
    const float2 v = *(const float2*)(ze + (size_t)w * DD + lane * 2);
    float ss = warpsum(v.x * v.x + v.y * v.y);
    float den = fmaxf(sqrtf(ss), EPSV);
    float2 o = make_float2(v.x / den, v.y / den);
    *(float2*)(g_zn + (size_t)w * DD + lane * 2) = o;
    if (lane == 0) g_znorm[w] = den;
}

// ---------------- kernel 2: normalize embedding rows -> transposed layout ----------------
__global__ void k_norm_e(const float* __restrict__ emb) {
    int w = (blockIdx.x * blockDim.x + threadIdx.x) >> 5;
    int lane = threadIdx.x & 31;
    if (w >= KK) return;
    const float2 v = *(const float2*)(emb + (size_t)w * DD + lane * 2);
    float ss = warpsum(v.x * v.x + v.y * v.y);
    float den = fmaxf(sqrtf(ss), EPSV);
    g_enT[(2 * lane + 0) * KK + w] = v.x / den;
    g_enT[(2 * lane + 1) * KK + w] = v.y / den;
}

// ---------------- kernel 3: zero scatter scratch ----------------
__global__ void k_zero() {
    int i = blockIdx.x * blockDim.x + threadIdx.x;
    if (i < KK) g_counts[i] = 0.0f;
    if (i < KK * DD) g_dw[i] = 0.0f;
}

// ---------------- kernel 4: fused sim GEMM + argmax + segment scatter ----------------
// CTA: 128 rows x full K (chunks of 64 cols). 256 threads = 16 row-groups x 16 col-groups,
// microtile 8 rows x 4 cols per thread. FMA:LDS ~ 10.7:1 -> FFMA-pipe-bound.
__global__ __launch_bounds__(256, 2) void k_sim() {
    __shared__ float4 znS[128][16];  // 32 KB  (later aliased by reduction buffers)
    __shared__ float4 enS[64][16];   // 16 KB  [d][c4] of current 64-col chunk

    const int tid = threadIdx.x;
    const int row0 = blockIdx.x * 128;

    // load z_n tile, coalesced float4
#pragma unroll
    for (int i = 0; i < 8; i++) {
        int idx = tid + i * 256;
        int r = idx >> 4, c = idx & 15;
        znS[r][c] = *(const float4*)(g_zn + (size_t)(row0 + r) * 64 + c * 4);
    }

    const int rg = tid >> 4, cg = tid & 15;
    const int r0 = rg * 8;

    float bestv[8];
    int   besti[8];
#pragma unroll
    for (int r = 0; r < 8; r++) { bestv[r] = -1e30f; besti[r] = 0; }

    for (int ch = 0; ch < 16; ch++) {
        __syncthreads();  // znS ready (iter 0) / previous compute done before refill
        // fill enS from transposed codebook: global coalesced, smem conflict-free
#pragma unroll
        for (int i = 0; i < 4; i++) {
            int idx = tid + i * 256;
            int d = idx >> 4, c = idx & 15;
            enS[d][c] = *(const float4*)(g_enT + d * KK + ch * 64 + c * 4);
        }
        __syncthreads();

        float acc[8][4];
#pragma unroll
        for (int r = 0; r < 8; r++)
#pragma unroll
            for (int j = 0; j < 4; j++) acc[r][j] = 0.0f;

#pragma unroll 4
        for (int dk = 0; dk < 16; dk++) {
            float4 b0 = enS[dk * 4 + 0][cg];
            float4 b1 = enS[dk * 4 + 1][cg];
            float4 b2 = enS[dk * 4 + 2][cg];
            float4 b3 = enS[dk * 4 + 3][cg];
#pragma unroll
            for (int r = 0; r < 8; r++) {
                float4 a = znS[r0 + r][dk];
                acc[r][0] += a.x * b0.x + a.y * b1.x + a.z * b2.x + a.w * b3.x;
                acc[r][1] += a.x * b0.y + a.y * b1.y + a.z * b2.y + a.w * b3.y;
                acc[r][2] += a.x * b0.z + a.y * b1.z + a.z * b2.z + a.w * b3.z;
                acc[r][3] += a.x * b0.w + a.y * b1.w + a.z * b2.w + a.w * b3.w;
            }
        }
        // fold into running argmax (idx ascending within thread -> strict > keeps first)
#pragma unroll
        for (int r = 0; r < 8; r++) {
#pragma unroll
            for (int j = 0; j < 4; j++) {
                float v = acc[r][j];
                int idx = ch * 64 + cg * 4 + j;
                if (v > bestv[r]) { bestv[r] = v; besti[r] = idx; }
            }
        }
    }
    __syncthreads();  // all compute reads of znS done -> safe to alias

    // cross-thread argmax reduction via smem aliased over znS
    unsigned long long* red = reinterpret_cast<unsigned long long*>(&znS[0][0]); // [128][16]
    int* codeS = reinterpret_cast<int*>(red + 128 * 16);                          // [128]
#pragma unroll
    for (int r = 0; r < 8; r++) {
        unsigned long long p =
            ((unsigned long long)__float_as_uint(bestv[r]) << 32) | (unsigned)besti[r];
        red[(r0 + r) * 16 + cg] = p;
    }
    __syncthreads();

    if (tid < 128) {
        float bv = -1e30f; int bi = 0x7fffffff;
#pragma unroll
        for (int c = 0; c < 16; c++) {
            unsigned long long p = red[tid * 16 + c];
            float v = __uint_as_float((unsigned)(p >> 32));
            int   i = (int)(unsigned)p;
            if (v > bv || (v == bv && i < bi)) { bv = v; bi = i; }
        }
        g_codes[row0 + tid] = bi;
        codeS[tid] = bi;
        atomicAdd(&g_counts[bi], 1.0f);
    }
    __syncthreads();

    // segment-sum scatter of z_n rows into dw (re-read z_n from global; znS is clobbered)
#pragma unroll
    for (int i = 0; i < 8; i++) {
        int t = tid + i * 256;
        int r = t >> 4, q = t & 15;
        int c = codeS[r];
        float4 v = *(const float4*)(g_zn + (size_t)(row0 + r) * 64 + q * 4);
        float* dst = g_dw + c * 64 + q * 4;
        atomicAdd(dst + 0, v.x);
        atomicAdd(dst + 1, v.y);
        atomicAdd(dst + 2, v.z);
        atomicAdd(dst + 3, v.w);
    }
}

// ---------------- kernel 5: EMA update + codebook re-normalize (1 CTA) ----------------
__global__ void k_ema(const float* __restrict__ ema_cs, const float* __restrict__ ema_w) {
    __shared__ float sred[1024];
    int k = threadIdx.x;
    float cs = ema_cs[k] * DECAYF + g_counts[k] * OMDF;
    sred[k] = cs;
    __syncthreads();
    for (int s = 512; s > 0; s >>= 1) {
        if (k < s) sred[k] += sred[k + s];
        __syncthreads();
    }
    float n = sred[0];
    float cluster = (cs + EPSV) / (n + KK * EPSV) * n;
    float den = fmaxf(cluster, EPSV);
    float ss = 0.0f;
    for (int d = 0; d < DD; d++) {
        float w = ema_w[k * DD + d] * DECAYF + g_dw[k * DD + d] * OMDF;
        float m = w / den;
        ss += m * m;
    }
    float nd = fmaxf(sqrtf(ss), EPSV);
    for (int d = 0; d < DD; d++) {
        float w = ema_w[k * DD + d] * DECAYF + g_dw[k * DD + d] * OMDF;
        float m = w / den;
        g_embed_unit[k * DD + d] = m / nd;
    }
}

// ---------------- kernel 6: gather + outputs (warp per row) ----------------
__global__ void k_out(const float* __restrict__ ze, float* __restrict__ out, int write_aux) {
    int w = (blockIdx.x * blockDim.x + threadIdx.x) >> 5;
    int lane = threadIdx.x & 31;
    if (w >= BB) return;
    int c = g_codes[w];
    float2 e = *(const float2*)(g_embed_unit + c * 64 + lane * 2);
    float ss = warpsum(e.x * e.x + e.y * e.y);
    float ed = fmaxf(sqrtf(ss), EPSV);
    float2 en = make_float2(e.x / ed, e.y / ed);
    float2 zn = *(const float2*)(g_zn + (size_t)w * 64 + lane * 2);
    float dot = warpsum(zn.x * en.x + zn.y * en.y);
    float zl = g_znorm[w];
    float2 zev = *(const float2*)(ze + (size_t)w * 64 + lane * 2);
    float2 zq = make_float2(e.x * zl, e.y * zl);
    // straight-through written literally as in reference: z_e + (z_q - z_e)
    float2 o = make_float2(zev.x + (zq.x - zev.x), zev.y + (zq.y - zev.y));
    *(float2*)(out + (size_t)w * 64 + lane * 2) = o;
    if (write_aux && lane == 0) {
        out[(size_t)BB * DD + w] = (float)c;             // codes (numeric cast)
        out[(size_t)BB * DD + BB + w] = 1.0f - dot;      // dists
    }
}

// ---------------- launcher ----------------
extern "C" void kernel_launch(void* const* d_in, const int* in_sizes, int n_in,
                              void* d_out, int out_size) {
    const float* ze  = (const float*)d_in[0];   // z_e           [B, 64]
    const float* emb = (const float*)d_in[1];   // embedding     [K, 64]
    const float* ecs = (const float*)d_in[2];   // ema_cluster   [K]
    const float* ew  = (const float*)d_in[3];   // ema_w         [K, 64]
    // tau (d_in[4]) is a positive scalar; argmax/dists/z_q are invariant to it.
    float* out = (float*)d_out;

    long long need = (long long)BB * DD + 2LL * BB;
    int write_aux = ((long long)out_size >= need) ? 1 : 0;

    k_norm_z<<<BB / 8, 256>>>(ze);
    k_norm_e<<<KK / 8, 256>>>(emb);
    k_zero<<<(KK * DD + 255) / 256, 256>>>();
    k_sim<<<BB / 128, 256>>>();
    k_ema<<<1, 1024>>>(ecs, ew);
    k_out<<<BB / 8, 256>>>(ze, out, write_aux);
}

// round 4
// speedup vs baseline: 1.5991x; 1.5991x over previous
#include <cuda_runtime.h>
#include <math.h>

// Problem constants (fixed shapes per reference)
#define BB 131072
#define DD 64
#define KK 1024
#define DECAYF 0.99f
#define OMDF 0.01f
#define EPSV 1e-5f

// ---------------- scratch (static __device__) ----------------
__device__ float g_znorm[BB];                // max(||z||, eps) per row
__device__ float g_enT[DD * KK];             // normalized embedding, TRANSPOSED [d][k]
__device__ float g_counts[KK];               // segment counts (float)
__device__ float g_dw[KK * DD];              // segment sums of z_n
__device__ float g_embed_unit[KK * DD];      // updated normalized codebook
__device__ int   g_codes[BB];                // argmax codes

// ---------------- helpers ----------------
__device__ __forceinline__ float warpsum(float v) {
#pragma unroll
    for (int o = 16; o; o >>= 1) v += __shfl_xor_sync(0xffffffffu, v, o);
    return v;
}
__device__ __forceinline__ float group16sum(float v) {
#pragma unroll
    for (int o = 8; o; o >>= 1) v += __shfl_xor_sync(0xffffffffu, v, o);
    return v;
}
__device__ __forceinline__ unsigned long long dupf(float x) {
    unsigned long long r;
    asm("mov.b64 %0, {%1, %1};" : "=l"(r) : "r"(__float_as_uint(x)));
    return r;
}
__device__ __forceinline__ void fma2(unsigned long long& acc,
                                     unsigned long long a, unsigned long long b) {
    asm("fma.rn.f32x2 %0, %1, %2, %0;" : "+l"(acc) : "l"(a), "l"(b));
}
__device__ __forceinline__ void unpack2(unsigned long long v, float& lo, float& hi) {
    asm("mov.b64 {%0, %1}, %2;" : "=f"(lo), "=f"(hi) : "l"(v));
}

// znT smem addressing with XOR swizzle on the 8-row block index.
// element (d, r):  d*128 + ((r>>3) ^ (d & 15))*8 + (r & 7)
__device__ __forceinline__ int znt_idx(int d, int r) {
    return d * 128 + ((((r >> 3) ^ d) & 15) << 3) + (r & 7);
}

// ---------------- kernel 1: prep = zero scatter scratch + normalize embedding ----------------
#define ZERO_BLOCKS 260   // ceil((KK*DD + KK) / 256) = 260
__global__ void k_prep(const float* __restrict__ emb) {
    int bid = blockIdx.x;
    if (bid < ZERO_BLOCKS) {
        int idx = bid * 256 + threadIdx.x;
        if (idx < KK * DD) g_dw[idx] = 0.0f;
        else if (idx < KK * DD + KK) g_counts[idx - KK * DD] = 0.0f;
        return;
    }
    // embedding normalize -> transposed layout, warp per row
    int w = (bid - ZERO_BLOCKS) * 8 + (threadIdx.x >> 5);
    int lane = threadIdx.x & 31;
    if (w >= KK) return;
    const float2 v = *(const float2*)(emb + (size_t)w * DD + lane * 2);
    float ss = warpsum(v.x * v.x + v.y * v.y);
    float den = fmaxf(sqrtf(ss), EPSV);
    g_enT[(2 * lane + 0) * KK + w] = v.x / den;
    g_enT[(2 * lane + 1) * KK + w] = v.y / den;
}

// ---------------- kernel 2: fused normalize + sim GEMM (FFMA2) + argmax + scatter ----------------
// CTA: 128 rows x full K (16 chunks of 64 cols). 256 threads = 16 row-groups x 16 col-groups.
// Thread microtile: 8 rows (4 row-PAIRS, packed f32x2) x 4 cols.
__global__ __launch_bounds__(256, 2) void k_sim(const float* __restrict__ ze) {
    __shared__ __align__(16) float znT[64 * 128];   // 32 KB, transposed normalized rows (swizzled)
    __shared__ union __align__(16) {
        float enS[64 * 64];                         // 16 KB, current 64-col chunk [d][c]
        int   codeS[128];
    } u;

    const int tid = threadIdx.x;
    const int row0 = blockIdx.x * 128;

    // ---- phase 1: load z_e tile, normalize rows (16-lane shfl), transpose into znT ----
#pragma unroll
    for (int i = 0; i < 8; i++) {
        int idx = tid + i * 256;
        int r = idx >> 4, c = idx & 15;
        float4 v = *(const float4*)(ze + (size_t)(row0 + r) * 64 + c * 4);
        float ss = group16sum(v.x * v.x + v.y * v.y + v.z * v.z + v.w * v.w);
        float den = fmaxf(sqrtf(ss), EPSV);
        float inv = 1.0f / den;
        if ((idx & 15) == 0) g_znorm[row0 + r] = den;
        znT[znt_idx(4 * c + 0, r)] = v.x * inv;
        znT[znt_idx(4 * c + 1, r)] = v.y * inv;
        znT[znt_idx(4 * c + 2, r)] = v.z * inv;
        znT[znt_idx(4 * c + 3, r)] = v.w * inv;
    }

    const int rg = tid >> 4, cg = tid & 15;

    float bestv[8];
    int   besti[8];
#pragma unroll
    for (int r = 0; r < 8; r++) { bestv[r] = -1e30f; besti[r] = 0; }

    // prefetch chunk 0 of enT into registers
    float4 pf[4];
#pragma unroll
    for (int i = 0; i < 4; i++) {
        int idx = tid + i * 256;
        int d = idx >> 4, c = idx & 15;
        pf[i] = *(const float4*)(g_enT + d * KK + c * 4);
    }

    for (int ch = 0; ch < 16; ch++) {
        __syncthreads();  // znT ready (iter0) / prev compute done reading enS
#pragma unroll
        for (int i = 0; i < 4; i++) {
            int idx = tid + i * 256;
            int d = idx >> 4, c = idx & 15;
            *(float4*)(u.enS + d * 64 + c * 4) = pf[i];
        }
        __syncthreads();
        if (ch < 15) {
#pragma unroll
            for (int i = 0; i < 4; i++) {
                int idx = tid + i * 256;
                int d = idx >> 4, c = idx & 15;
                pf[i] = *(const float4*)(g_enT + d * KK + (ch + 1) * 64 + c * 4);
            }
        }

        unsigned long long acc[4][4];
#pragma unroll
        for (int p = 0; p < 4; p++)
#pragma unroll
            for (int j = 0; j < 4; j++) acc[p][j] = 0ULL;

#pragma unroll 4
        for (int d = 0; d < 64; d++) {
            int ai = d * 128 + (((rg ^ d) & 15) << 3);
            ulonglong2 a01 = *(const ulonglong2*)(znT + ai);      // rows 8rg+0..3 (2 pairs)
            ulonglong2 a23 = *(const ulonglong2*)(znT + ai + 4);  // rows 8rg+4..7 (2 pairs)
            float4 bq = *(const float4*)(u.enS + d * 64 + cg * 4);
            unsigned long long b0 = dupf(bq.x), b1 = dupf(bq.y),
                               b2 = dupf(bq.z), b3 = dupf(bq.w);
            fma2(acc[0][0], a01.x, b0); fma2(acc[0][1], a01.x, b1);
            fma2(acc[0][2], a01.x, b2); fma2(acc[0][3], a01.x, b3);
            fma2(acc[1][0], a01.y, b0); fma2(acc[1][1], a01.y, b1);
            fma2(acc[1][2], a01.y, b2); fma2(acc[1][3], a01.y, b3);
            fma2(acc[2][0], a23.x, b0); fma2(acc[2][1], a23.x, b1);
            fma2(acc[2][2], a23.x, b2); fma2(acc[2][3], a23.x, b3);
            fma2(acc[3][0], a23.y, b0); fma2(acc[3][1], a23.y, b1);
            fma2(acc[3][2], a23.y, b2); fma2(acc[3][3], a23.y, b3);
        }

        // fold into running argmax (col idx ascending within thread -> strict > keeps first)
#pragma unroll
        for (int p = 0; p < 4; p++) {
#pragma unroll
            for (int j = 0; j < 4; j++) {
                float lo, hi;
                unpack2(acc[p][j], lo, hi);
                int idx = ch * 64 + cg * 4 + j;
                if (lo > bestv[2 * p])     { bestv[2 * p]     = lo; besti[2 * p]     = idx; }
                if (hi > bestv[2 * p + 1]) { bestv[2 * p + 1] = hi; besti[2 * p + 1] = idx; }
            }
        }
    }
    __syncthreads();  // done reading enS -> safe to alias with codeS

    // ---- cross-lane argmax: butterfly over the 16 lanes of each row-group ----
#pragma unroll
    for (int r = 0; r < 8; r++) {
        unsigned long long p =
            ((unsigned long long)__float_as_uint(bestv[r]) << 32) | (unsigned)besti[r];
#pragma unroll
        for (int o = 8; o; o >>= 1) {
            unsigned long long q = __shfl_xor_sync(0xffffffffu, p, o);
            float qv = __uint_as_float((unsigned)(q >> 32));
            float pv = __uint_as_float((unsigned)(p >> 32));
            int qi = (int)(unsigned)q, pi = (int)(unsigned)p;
            if (qv > pv || (qv == pv && qi < pi)) p = q;
        }
        if (cg == 0) {
            int code = (int)(unsigned)p;
            int row = 8 * rg + r;
            g_codes[row0 + row] = code;
            u.codeS[row] = code;
            atomicAdd(&g_counts[code], 1.0f);
        }
    }
    __syncthreads();

    // ---- segment-sum scatter of normalized rows (from znT) into g_dw ----
#pragma unroll
    for (int i = 0; i < 8; i++) {
        int item = tid + i * 256;
        int r = item >> 4, dq = item & 15;
        int code = u.codeS[r];
#pragma unroll
        for (int j = 0; j < 4; j++) {
            int d = 4 * dq + j;
            atomicAdd(&g_dw[code * 64 + d], znT[znt_idx(d, r)]);
        }
    }
}

// ---------------- kernel 3: EMA update + codebook re-normalize (1 CTA, coalesced) ----------------
__global__ void k_ema(const float* __restrict__ ema_cs, const float* __restrict__ ema_w) {
    __shared__ float sred[1024];
    __shared__ float invden[1024];
    int k = threadIdx.x;
    float cs = ema_cs[k] * DECAYF + g_counts[k] * OMDF;
    sred[k] = cs;
    __syncthreads();
    for (int s = 512; s > 0; s >>= 1) {
        if (k < s) sred[k] += sred[k + s];
        __syncthreads();
    }
    float n = sred[0];
    float cluster = (cs + EPSV) / (n + KK * EPSV) * n;
    invden[k] = 1.0f / fmaxf(cluster, EPSV);
    __syncthreads();

    int lane = k & 15;
#pragma unroll 1
    for (int g = 0; g < 16; g++) {
        int k2 = (g << 6) + (k >> 4);
        float inv = invden[k2];
        float4 w = *(const float4*)(ema_w + k2 * 64 + lane * 4);
        float4 dv = *(const float4*)(g_dw + k2 * 64 + lane * 4);
        float4 m;
        m.x = (w.x * DECAYF + dv.x * OMDF) * inv;
        m.y = (w.y * DECAYF + dv.y * OMDF) * inv;
        m.z = (w.z * DECAYF + dv.z * OMDF) * inv;
        m.w = (w.w * DECAYF + dv.w * OMDF) * inv;
        float ss = group16sum(m.x * m.x + m.y * m.y + m.z * m.z + m.w * m.w);
        float ni = 1.0f / fmaxf(sqrtf(ss), EPSV);
        float4 o = make_float4(m.x * ni, m.y * ni, m.z * ni, m.w * ni);
        *(float4*)(g_embed_unit + k2 * 64 + lane * 4) = o;
    }
}

// ---------------- kernel 4: gather + outputs (warp per row) ----------------
__global__ void k_out(const float* __restrict__ ze, float* __restrict__ out, int write_aux) {
    int w = (blockIdx.x * blockDim.x + threadIdx.x) >> 5;
    int lane = threadIdx.x & 31;
    if (w >= BB) return;
    int c = g_codes[w];
    float zl = g_znorm[w];
    float zinv = 1.0f / zl;
    float2 e = *(const float2*)(g_embed_unit + c * 64 + lane * 2);
    float ss = warpsum(e.x * e.x + e.y * e.y);
    float ed = fmaxf(sqrtf(ss), EPSV);
    float2 en = make_float2(e.x / ed, e.y / ed);
    float2 zev = *(const float2*)(ze + (size_t)w * 64 + lane * 2);
    float2 zn = make_float2(zev.x * zinv, zev.y * zinv);
    float dot = warpsum(zn.x * en.x + zn.y * en.y);
    float2 zq = make_float2(e.x * zl, e.y * zl);
    float2 o = make_float2(zev.x + (zq.x - zev.x), zev.y + (zq.y - zev.y));
    *(float2*)(out + (size_t)w * 64 + lane * 2) = o;
    if (write_aux && lane == 0) {
        out[(size_t)BB * DD + w] = (float)c;          // codes (numeric cast)
        out[(size_t)BB * DD + BB + w] = 1.0f - dot;   // dists
    }
}

// ---------------- launcher ----------------
extern "C" void kernel_launch(void* const* d_in, const int* in_sizes, int n_in,
                              void* d_out, int out_size) {
    const float* ze  = (const float*)d_in[0];   // z_e           [B, 64]
    const float* emb = (const float*)d_in[1];   // embedding     [K, 64]
    const float* ecs = (const float*)d_in[2];   // ema_cluster   [K]
    const float* ew  = (const float*)d_in[3];   // ema_w         [K, 64]
    float* out = (float*)d_out;

    long long need = (long long)BB * DD + 2LL * BB;
    int write_aux = ((long long)out_size >= need) ? 1 : 0;

    k_prep<<<ZERO_BLOCKS + KK / 8, 256>>>(emb);
    k_sim<<<BB / 128, 256>>>(ze);
    k_ema<<<1, 1024>>>(ecs, ew);
    k_out<<<BB / 8, 256>>>(ze, out, write_aux);
}